// round 2
// baseline (speedup 1.0000x reference)
#include <cuda_runtime.h>

#define H  128
#define W  256
#define HW 32768
#define C  64
#define FH 128      // cube face size

// ---------------- scratch (device globals; no allocation allowed) ----------------
__device__ float g_aux [4*C*HW];
__device__ float g_main[4*C*HW];
__device__ float g_maux[4*C*HW];
__device__ int   g_geo[HW];
__device__ float g_dx[HW];
__device__ float g_dy[HW];

// ---------------- packed f32x2 helpers (Blackwell) ----------------
typedef unsigned long long u64;
__device__ __forceinline__ u64 pack2(float a, float b) {
    u64 r; asm("mov.b64 %0, {%1, %2};" : "=l"(r) : "f"(a), "f"(b)); return r;
}
__device__ __forceinline__ void ffma2(u64& d, u64 a, u64 b) {
    asm("fma.rn.f32x2 %0, %1, %2, %0;" : "+l"(d) : "l"(a), "l"(b));
}
__device__ __forceinline__ float2 unpack2(u64 v) {
    float2 r; asm("mov.b64 {%0, %1}, %2;" : "=f"(r.x), "=f"(r.y) : "l"(v)); return r;
}

// ---------------- 1) per-pixel cube geometry ----------------
__global__ void geom_kernel() {
    int p = blockIdx.x * blockDim.x + threadIdx.x;
    if (p >= HW) return;
    int i = p >> 8;          // row   (H=128)
    int j = p & 255;         // col   (W=256)
    const float PI = 3.14159265358979323846f;
    float lat = (0.5f - (i + 0.5f) / 128.f) * PI;
    float lon = (2.f * (j + 0.5f) / 256.f - 1.f) * PI;
    float cl = cosf(lat);
    float vx = cl * sinf(lon);
    float vy = sinf(lat);
    float vz = cl * cosf(lon);
    float ax = fabsf(vx), ay = fabsf(vy), az = fabsf(vz);
    bool cond_z = (az >= ax) && (az >= ay);
    bool cond_x = (!cond_z) && (ax >= ay);
    int face;
    if (cond_z)      face = (vz > 0.f) ? 2 : 0;
    else if (cond_x) face = (vx > 0.f) ? 4 : 3;
    else             face = (vy > 0.f) ? 5 : 1;

    float den, a, bc;
    switch (face) {
        case 0: den = -vz; a = -vx / den; bc =  vy / den; break;  // back
        case 1: den = -vy; a =  vx / den; bc = -vz / den; break;  // down
        case 2: den =  vz; a =  vx / den; bc =  vy / den; break;  // front
        case 3: den = -vx; a =  vz / den; bc =  vy / den; break;  // left
        case 4: den =  vx; a = -vz / den; bc =  vy / den; break;  // right
        default:den =  vy; a =  vx / den; bc =  vz / den; break;  // up
    }
    float uu = fminf(fmaxf((a   + 1.f) * 0.5f * 127.f, 0.f), 127.f);
    float vv = fminf(fmaxf((1.f - bc ) * 0.5f * 127.f, 0.f), 127.f);
    int x0 = (int)floorf(uu);
    int y0 = (int)floorf(vv);
    int x1 = min(x0 + 1, 127);
    int y1 = min(y0 + 1, 127);
    g_geo[p] = face | (x0 << 3) | (y0 << 10) | (x1 << 17) | (y1 << 24);
    g_dx[p] = uu - (float)x0;
    g_dy[p] = vv - (float)y0;
}

// ---------------- 2) bilinear cube gather -> aux ----------------
__global__ __launch_bounds__(256) void gather_kernel(
    const float* __restrict__ fb, const float* __restrict__ fd,
    const float* __restrict__ ff, const float* __restrict__ fl,
    const float* __restrict__ fr, const float* __restrict__ fu)
{
    int idx = blockIdx.x * 256 + threadIdx.x;     // bc*HW + p
    int p  = idx & (HW - 1);
    int bc = idx >> 15;
    int geo = g_geo[p];
    int face = geo & 7;
    int x0 = (geo >> 3)  & 127;
    int y0 = (geo >> 10) & 127;
    int x1 = (geo >> 17) & 127;
    int y1 = (geo >> 24) & 127;
    float dx = g_dx[p], dy = g_dy[p];
    const float* fp;
    switch (face) {
        case 0: fp = fb; break;
        case 1: fp = fd; break;
        case 2: fp = ff; break;
        case 3: fp = fl; break;
        case 4: fp = fr; break;
        default: fp = fu; break;
    }
    fp += (size_t)bc * (FH * FH);
    float v00 = fp[y0 * FH + x0];
    float v01 = fp[y0 * FH + x1];
    float v10 = fp[y1 * FH + x0];
    float v11 = fp[y1 * FH + x1];
    float r = v00 * ((1.f - dx) * (1.f - dy))
            + v01 * (dx * (1.f - dy))
            + v10 * ((1.f - dx) * dy)
            + v11 * (dx * dy);
    g_aux[idx] = r;
}

// ---------------- 3) 3x3 conv + relu (shared weights), f32x2 packed ----------------
#define OCB 16
#define ICB 2
#define TW  64
#define TH  8

__global__ __launch_bounds__(128) void conv3_relu(
    const float* __restrict__ xin, int which,
    const float* __restrict__ wt, const float* __restrict__ bias)
{
    __shared__ float wsh[C * 9 * OCB];                       // 36864 B  [ic][k][oc16]
    __shared__ __align__(16) float xs[ICB * (TH + 2) * 68];  // 5440 B

    const int tid = threadIdx.x;
    const int bx  = blockIdx.x & 3;        // W tiles: 256/64
    const int by  = blockIdx.x >> 2;       // H tiles: 128/8
    const int oc0 = blockIdx.y * OCB;
    const int b   = blockIdx.z;

    const float* __restrict__ x = which ? g_aux  : xin;
    float*       __restrict__ y = which ? g_maux : g_main;

    // stage weights for this oc-group: layout [(ic*9 + k)*16 + o]
    for (int t = tid; t < C * 9 * OCB; t += 128) {
        int o  = t & 15;
        int k  = (t >> 4) % 9;
        int ic = t / (9 * OCB);
        wsh[t] = wt[((oc0 + o) * C + ic) * 9 + k];
    }

    const int tx = tid & 15;    // 16 -> 4 px each = 64 W
    const int ty = tid >> 4;    // 8 rows
    const float* xb = x + (size_t)b * C * HW;

    u64 acc[4][8];
    #pragma unroll
    for (int j = 0; j < 8; j++) {
        u64 bz = pack2(bias[oc0 + 2*j], bias[oc0 + 2*j + 1]);
        #pragma unroll
        for (int p = 0; p < 4; p++) acc[p][j] = bz;
    }

    for (int c0 = 0; c0 < C; c0 += ICB) {
        __syncthreads();
        // input tile with halo: 2 ic x 10 rows x 66 cols (padded stride 68)
        for (int t = tid; t < ICB * (TH + 2) * 66; t += 128) {
            int cc = t % 66;
            int rr = (t / 66) % (TH + 2);
            int ic = t / (66 * (TH + 2));
            int gy = by * TH - 1 + rr;
            int gx = bx * TW - 1 + cc;
            float v = 0.f;
            if ((unsigned)gy < H && (unsigned)gx < W)
                v = xb[(size_t)(c0 + ic) * HW + gy * W + gx];
            xs[(ic * (TH + 2) + rr) * 68 + cc] = v;
        }
        __syncthreads();

        #pragma unroll
        for (int ic = 0; ic < ICB; ic++) {
            #pragma unroll
            for (int ky = 0; ky < 3; ky++) {
                const float* row = &xs[(ic * (TH + 2) + ty + ky) * 68 + tx * 4];
                float4 v4 = *(const float4*)row;
                float w4 = row[4], w5 = row[5];
                u64 iv[6];
                iv[0] = pack2(v4.x, v4.x);
                iv[1] = pack2(v4.y, v4.y);
                iv[2] = pack2(v4.z, v4.z);
                iv[3] = pack2(v4.w, v4.w);
                iv[4] = pack2(w4, w4);
                iv[5] = pack2(w5, w5);
                const u64* wr = (const u64*)&wsh[((c0 + ic) * 9 + ky * 3) * OCB];
                #pragma unroll
                for (int kx = 0; kx < 3; kx++) {
                    #pragma unroll
                    for (int j = 0; j < 8; j++) {
                        u64 wv = wr[kx * 8 + j];
                        #pragma unroll
                        for (int p = 0; p < 4; p++)
                            ffma2(acc[p][j], iv[p + kx], wv);
                    }
                }
            }
        }
    }

    const int oy = by * TH + ty;
    const int ox = bx * TW + tx * 4;
    float* yb = y + (((size_t)b * C + oc0) * H + oy) * W + ox;
    #pragma unroll
    for (int j = 0; j < 8; j++) {
        float2 r0 = unpack2(acc[0][j]);
        float2 r1 = unpack2(acc[1][j]);
        float2 r2 = unpack2(acc[2][j]);
        float2 r3 = unpack2(acc[3][j]);
        float4 lo = make_float4(fmaxf(r0.x,0.f), fmaxf(r1.x,0.f), fmaxf(r2.x,0.f), fmaxf(r3.x,0.f));
        float4 hi = make_float4(fmaxf(r0.y,0.f), fmaxf(r1.y,0.f), fmaxf(r2.y,0.f), fmaxf(r3.y,0.f));
        *(float4*)(yb + (size_t)(2*j    ) * HW) = lo;
        *(float4*)(yb + (size_t)(2*j + 1) * HW) = hi;
    }
}

// ---------------- 4) 1x1 mask conv + sigmoid + blend ----------------
__global__ __launch_bounds__(256) void mask_out_kernel(
    const float* __restrict__ m, const float* __restrict__ wm,
    const float* __restrict__ bm, float* __restrict__ out)
{
    __shared__ float ws[128];
    if (threadIdx.x < 128) ws[threadIdx.x] = wm[threadIdx.x];
    __syncthreads();
    int idx = blockIdx.x * 256 + threadIdx.x;   // b*HW + p
    int p = idx & (HW - 1);
    int b = idx >> 15;
    const float* pm = g_main + ((size_t)b << 21) + p;
    const float* pa = g_maux + ((size_t)b << 21) + p;
    float s = bm[0];
    #pragma unroll
    for (int c = 0; c < 64; c++)
        s += ws[c] * pm[c << 15] + ws[64 + c] * pa[c << 15];
    float mk = 1.f / (1.f + expf(-s));
    const float* pmm = m + ((size_t)b << 21) + p;
    float* po = out + ((size_t)b << 21) + p;
    #pragma unroll
    for (int c = 0; c < 64; c++)
        po[c << 15] = pmm[c << 15] + mk * pa[c << 15];
}

// ---------------- launch ----------------
extern "C" void kernel_launch(void* const* d_in, const int* in_sizes, int n_in,
                              void* d_out, int out_size)
{
    const float* m  = (const float*)d_in[0];
    const float* f  = (const float*)d_in[1];
    const float* r  = (const float*)d_in[2];
    const float* bb = (const float*)d_in[3];
    const float* l  = (const float*)d_in[4];
    const float* u  = (const float*)d_in[5];
    const float* d  = (const float*)d_in[6];
    const float* wf = (const float*)d_in[7];
    const float* bf = (const float*)d_in[8];
    const float* wm = (const float*)d_in[9];
    const float* bm = (const float*)d_in[10];
    float* out = (float*)d_out;

    geom_kernel<<<128, 256>>>();
    gather_kernel<<<4 * C * HW / 256, 256>>>(bb, d, f, l, r, u);
    dim3 cgrid(64, 4, 4);                 // (bx,by) x oc-groups x batch
    conv3_relu<<<cgrid, 128>>>(m, 0, wf, bf);        // m -> g_main
    conv3_relu<<<cgrid, 128>>>(nullptr, 1, wf, bf);  // aux -> g_maux
    mask_out_kernel<<<4 * HW / 256, 256>>>(m, wm, bm, out);
}

// round 4
// speedup vs baseline: 1.6188x; 1.6188x over previous
#include <cuda_runtime.h>
#include <cstdint>

#define H   128
#define W   256
#define HW  32768
#define FH  128
#define XPH 130
#define XPW 258
#define PLANE (XPH*XPW*32)

// ---------------- scratch (device globals; no allocation allowed) ----------------
__device__ float g_xm[8*PLANE];     // m, padded NHWC (2x 32ch planes per batch), tf32-rounded
__device__ float g_xa[8*PLANE];     // aux, same layout
__device__ float g_wt[18*2048];     // weights [chunk(icc,tap)][oc64][ic32], tf32-rounded
__device__ int   g_geo[HW];
__device__ float g_dx[HW];
__device__ float g_dy[HW];

// ---------------- helpers ----------------
__device__ __forceinline__ float tf32r(float v) {
    float r; asm("cvt.rna.tf32.f32 %0, %1;" : "=f"(r) : "f"(v)); return r;
}
__device__ __forceinline__ uint32_t smem_u32(const void* p) {
    uint32_t a;
    asm("{ .reg .u64 t; cvta.to.shared.u64 t, %1; cvt.u32.u64 %0, t; }" : "=r"(a) : "l"(p));
    return a;
}
__device__ __forceinline__ void cp16(uint32_t dst, const float* src) {
    unsigned long long g = (unsigned long long)__cvta_generic_to_global((const void*)src);
    asm volatile("cp.async.cg.shared.global [%0], [%1], 16;" :: "r"(dst), "l"(g) : "memory");
}
__device__ __forceinline__ void mma8(float* d, const uint32_t* a, const uint32_t* b) {
    asm volatile(
        "mma.sync.aligned.m16n8k8.row.col.f32.tf32.tf32.f32 "
        "{%0,%1,%2,%3}, {%4,%5,%6,%7}, {%8,%9}, {%0,%1,%2,%3};"
        : "+f"(d[0]), "+f"(d[1]), "+f"(d[2]), "+f"(d[3])
        : "r"(a[0]), "r"(a[1]), "r"(a[2]), "r"(a[3]), "r"(b[0]), "r"(b[1]));
}

// ---------------- 1) per-pixel cube geometry ----------------
__global__ void geom_kernel() {
    int p = blockIdx.x * blockDim.x + threadIdx.x;
    if (p >= HW) return;
    int i = p >> 8;
    int j = p & 255;
    const float PI = 3.14159265358979323846f;
    float lat = (0.5f - (i + 0.5f) / 128.f) * PI;
    float lon = (2.f * (j + 0.5f) / 256.f - 1.f) * PI;
    float cl = cosf(lat);
    float vx = cl * sinf(lon);
    float vy = sinf(lat);
    float vz = cl * cosf(lon);
    float ax = fabsf(vx), ay = fabsf(vy), az = fabsf(vz);
    bool cond_z = (az >= ax) && (az >= ay);
    bool cond_x = (!cond_z) && (ax >= ay);
    int face;
    if (cond_z)      face = (vz > 0.f) ? 2 : 0;
    else if (cond_x) face = (vx > 0.f) ? 4 : 3;
    else             face = (vy > 0.f) ? 5 : 1;
    float den, a, bc;
    switch (face) {
        case 0: den = -vz; a = -vx / den; bc =  vy / den; break;
        case 1: den = -vy; a =  vx / den; bc = -vz / den; break;
        case 2: den =  vz; a =  vx / den; bc =  vy / den; break;
        case 3: den = -vx; a =  vz / den; bc =  vy / den; break;
        case 4: den =  vx; a = -vz / den; bc =  vy / den; break;
        default:den =  vy; a =  vx / den; bc =  vz / den; break;
    }
    float uu = fminf(fmaxf((a   + 1.f) * 0.5f * 127.f, 0.f), 127.f);
    float vv = fminf(fmaxf((1.f - bc ) * 0.5f * 127.f, 0.f), 127.f);
    int x0 = (int)floorf(uu);
    int y0 = (int)floorf(vv);
    int x1 = min(x0 + 1, 127);
    int y1 = min(y0 + 1, 127);
    g_geo[p] = face | (x0 << 3) | (y0 << 10) | (x1 << 17) | (y1 << 24);
    g_dx[p] = uu - (float)x0;
    g_dy[p] = vv - (float)y0;
}

// ---------------- 2) zero padded borders ----------------
__global__ void pad_kernel() {
    const int PER = 24704;
    int t = blockIdx.x * 256 + threadIdx.x;
    if (t >= 2 * 8 * PER) return;
    float* base = (t < 8 * PER) ? g_xm : g_xa;
    int r = t % (8 * PER);
    int plane = r / PER;
    int e = r % PER;
    int y, x, ic;
    if (e < 16512) {
        y = (e < 8256) ? 0 : 129;
        int o = e % 8256; x = o >> 5; ic = o & 31;
    } else {
        int e2 = e - 16512;
        x = (e2 < 4096) ? 0 : 257;
        int o = e2 & 4095; y = 1 + (o >> 5); ic = o & 31;
    }
    base[((size_t)(plane * XPH + y) * XPW + x) * 32 + ic] = 0.f;
}

// ---------------- 3) weights -> [chunk][oc][ic32], tf32-rounded ----------------
__global__ void wtprep_kernel(const float* __restrict__ wf) {
    int idx = blockIdx.x * 256 + threadIdx.x;
    if (idx >= 18 * 2048) return;
    int ch = idx >> 11, rr = idx & 2047;
    int oc = rr >> 5, ic = rr & 31;
    int icc = ch / 9, kk = ch % 9;
    g_wt[idx] = tf32r(wf[(oc * 64 + icc * 32 + ic) * 9 + kk]);
}

// ---------------- 4) m: NCHW -> padded NHWC (tf32) ----------------
__global__ __launch_bounds__(256) void nchw2xp_kernel(const float* __restrict__ m) {
    __shared__ float sm[64][33];
    int blk = blockIdx.x;                        // b*1024 + y*8 + xt
    int xt = blk & 7, y = (blk >> 3) & 127, b = blk >> 10;
    int tid = threadIdx.x;
    int xl = tid & 31, cw = tid >> 5;
    #pragma unroll
    for (int k = 0; k < 8; k++) {
        int c = cw + k * 8;
        sm[c][xl] = m[(((size_t)(b * 64 + c)) * 128 + y) * 256 + xt * 32 + xl];
    }
    __syncthreads();
    for (int i = tid; i < 2048; i += 256) {
        int px = i >> 6, c = i & 63, icc = c >> 5;
        g_xm[(((size_t)((b * 2 + icc) * XPH) + y + 1) * XPW + xt * 32 + px + 1) * 32 + (c & 31)]
            = tf32r(sm[c][px]);
    }
}

// ---------------- 5) bilinear cube gather -> padded NHWC aux (tf32) ----------------
__global__ __launch_bounds__(256) void gather_kernel(
    const float* __restrict__ fb, const float* __restrict__ fd,
    const float* __restrict__ ff, const float* __restrict__ fl,
    const float* __restrict__ fr, const float* __restrict__ fu)
{
    __shared__ float sm[64][33];
    int blk = blockIdx.x;
    int xt = blk & 7, y = (blk >> 3) & 127, b = blk >> 10;
    int tid = threadIdx.x;
    int xl = tid & 31, cw = tid >> 5;
    int p = y * 256 + xt * 32 + xl;
    int geo = g_geo[p];
    int face = geo & 7;
    int x0 = (geo >> 3) & 127, y0 = (geo >> 10) & 127;
    int x1 = (geo >> 17) & 127, y1 = (geo >> 24) & 127;
    float dx = g_dx[p], dy = g_dy[p];
    float w00 = (1.f - dx) * (1.f - dy), w01 = dx * (1.f - dy);
    float w10 = (1.f - dx) * dy,         w11 = dx * dy;
    const float* fp0;
    switch (face) {
        case 0: fp0 = fb; break; case 1: fp0 = fd; break; case 2: fp0 = ff; break;
        case 3: fp0 = fl; break; case 4: fp0 = fr; break; default: fp0 = fu; break;
    }
    #pragma unroll
    for (int k = 0; k < 8; k++) {
        int c = cw + k * 8;
        const float* fp = fp0 + ((size_t)(b * 64 + c)) * (FH * FH);
        sm[c][xl] = fp[y0 * FH + x0] * w00 + fp[y0 * FH + x1] * w01
                  + fp[y1 * FH + x0] * w10 + fp[y1 * FH + x1] * w11;
    }
    __syncthreads();
    for (int i = tid; i < 2048; i += 256) {
        int px = i >> 6, c = i & 63, icc = c >> 5;
        g_xa[(((size_t)((b * 2 + icc) * XPH) + y + 1) * XPW + xt * 32 + px + 1) * 32 + (c & 31)]
            = tf32r(sm[c][px]);
    }
}

// ---------------- 6) fused: both convs (mma.sync tf32) + mask + blend ----------------
// smem floats: [0,4608) wt bufs (2 x 64x36); [4608,41472) px bufs (2 bufs x 2 slabs x 256x36)
//              [41472,41536) bias; [41536,41664) wm; [41664] bm
// epilogue reuse: stage 256x65 @4608; mask 256 @21248   (both inside px buf0, buf1 untouched)
#define SMEMB 166912

__global__ __launch_bounds__(256, 1) void fused_kernel(
    const float* __restrict__ m_in, const float* __restrict__ bfu,
    const float* __restrict__ wm,   const float* __restrict__ bm,
    float* __restrict__ out)
{
    extern __shared__ float sf[];
    const uint32_t sb = smem_u32(sf);
    const int tid = threadIdx.x;
    const int wid = tid >> 5;
    const int lane = tid & 31;
    const int r4 = lane >> 2, c4 = lane & 3;
    const int b = blockIdx.x >> 7;
    const int y = blockIdx.x & 127;

    if (tid < 64)  sf[41472 + tid] = bfu[tid];
    if (tid < 128) sf[41536 + tid] = wm[tid];
    if (tid == 0)  sf[41664] = bm[0];

    float acc[2][2][8][4];                       // [conv][mt][nt][frag]
    #pragma unroll
    for (int v = 0; v < 2; v++)
        #pragma unroll
        for (int mt = 0; mt < 2; mt++)
            #pragma unroll
            for (int nt = 0; nt < 8; nt++)
                #pragma unroll
                for (int e = 0; e < 4; e++) acc[v][mt][nt][e] = 0.f;

    auto fill = [&](int c) {
        int icc = c / 9, kk = c % 9, ky = kk / 3, kx = kk % 3;
        int rowoff = (((b * 2 + icc) * XPH + y + ky) * XPW + kx) * 32;
        const float* srcm = g_xm + rowoff;
        const float* srca = g_xa + rowoff;
        uint32_t dm = sb + 18432 + (c & 1) * 73728;
        uint32_t da = dm + 36864;
        #pragma unroll
        for (int i = 0; i < 8; i++) {
            int j = tid + i * 256;
            int px = j >> 3, q = j & 7;
            cp16(dm + px * 144 + q * 16, srcm + px * 32 + q * 4);
            cp16(da + px * 144 + q * 16, srca + px * 32 + q * 4);
        }
        const float* sw = g_wt + c * 2048;
        uint32_t dw = sb + (c & 1) * 9216;
        #pragma unroll
        for (int i = 0; i < 2; i++) {
            int j = tid + i * 256;
            int oc = j >> 3, q = j & 7;
            cp16(dw + oc * 144 + q * 16, sw + oc * 32 + q * 4);
        }
    };

    fill(0);
    asm volatile("cp.async.commit_group;" ::: "memory");

    for (int c = 0; c < 18; c++) {
        __syncthreads();                         // prior chunk's MMA done before overwrite
        if (c < 17) fill(c + 1);
        asm volatile("cp.async.commit_group;" ::: "memory");
        if (c < 17) asm volatile("cp.async.wait_group 1;" ::: "memory");
        else        asm volatile("cp.async.wait_group 0;" ::: "memory");
        __syncthreads();

        const float* wb  = sf + (c & 1) * 2304;
        const float* pmb = sf + 4608 + (c & 1) * 18432;
        const float* pab = pmb + 9216;

        #pragma unroll
        for (int ks = 0; ks < 4; ks++) {
            uint32_t bw[8][2];
            #pragma unroll
            for (int nt = 0; nt < 8; nt++) {
                const float* p = wb + (nt * 8 + r4) * 36 + ks * 8 + c4;
                bw[nt][0] = __float_as_uint(p[0]);
                bw[nt][1] = __float_as_uint(p[4]);
            }
            uint32_t am[2][4], aa[2][4];
            #pragma unroll
            for (int mt = 0; mt < 2; mt++) {
                int px = wid * 32 + mt * 16 + r4;
                const float* p0 = pmb + px * 36 + ks * 8 + c4;
                am[mt][0] = __float_as_uint(p0[0]);
                am[mt][1] = __float_as_uint(p0[288]);      // +8 rows * 36
                am[mt][2] = __float_as_uint(p0[4]);
                am[mt][3] = __float_as_uint(p0[292]);
                const float* p1 = pab + px * 36 + ks * 8 + c4;
                aa[mt][0] = __float_as_uint(p1[0]);
                aa[mt][1] = __float_as_uint(p1[288]);
                aa[mt][2] = __float_as_uint(p1[4]);
                aa[mt][3] = __float_as_uint(p1[292]);
            }
            #pragma unroll
            for (int mt = 0; mt < 2; mt++)
                #pragma unroll
                for (int nt = 0; nt < 8; nt++) {
                    mma8(acc[0][mt][nt], am[mt], bw[nt]);
                    mma8(acc[1][mt][nt], aa[mt], bw[nt]);
                }
        }
    }

    // ---------------- epilogue ----------------
    float* stage = sf + 4608;                    // [256][65] relu(aux)
    float* maskS = sf + 21248;                   // [256]
    const float* sbias = sf + 41472;
    const float* swm   = sf + 41536;
    const float  bmv   = sf[41664];

    float tot[2][2];
    #pragma unroll
    for (int mt = 0; mt < 2; mt++)
        #pragma unroll
        for (int h = 0; h < 2; h++) {
            float s = 0.f;
            int px = wid * 32 + mt * 16 + r4 + 8 * h;
            #pragma unroll
            for (int nt = 0; nt < 8; nt++)
                #pragma unroll
                for (int j = 0; j < 2; j++) {
                    int oc = nt * 8 + 2 * c4 + j;
                    float bv = sbias[oc];
                    float vm = fmaxf(acc[0][mt][nt][2 * h + j] + bv, 0.f);
                    float va = fmaxf(acc[1][mt][nt][2 * h + j] + bv, 0.f);
                    s += swm[oc] * vm + swm[64 + oc] * va;
                    stage[px * 65 + oc] = va;
                }
            tot[mt][h] = s;
        }
    #pragma unroll
    for (int mt = 0; mt < 2; mt++)
        #pragma unroll
        for (int h = 0; h < 2; h++) {
            float s = tot[mt][h];
            s += __shfl_xor_sync(0xffffffffu, s, 1);
            s += __shfl_xor_sync(0xffffffffu, s, 2);
            if (c4 == 0) {
                int px = wid * 32 + mt * 16 + r4 + 8 * h;
                maskS[px] = 1.f / (1.f + expf(-(s + bmv)));
            }
        }
    __syncthreads();

    float mk = maskS[tid];
    #pragma unroll 4
    for (int oc = 0; oc < 64; oc++) {
        size_t idx = (((size_t)(b * 64 + oc)) * 128 + y) * 256 + tid;
        out[idx] = m_in[idx] + mk * stage[tid * 65 + oc];
    }
}

// ---------------- launch ----------------
extern "C" void kernel_launch(void* const* d_in, const int* in_sizes, int n_in,
                              void* d_out, int out_size)
{
    const float* m  = (const float*)d_in[0];
    const float* f  = (const float*)d_in[1];
    const float* r  = (const float*)d_in[2];
    const float* bb = (const float*)d_in[3];
    const float* l  = (const float*)d_in[4];
    const float* u  = (const float*)d_in[5];
    const float* d  = (const float*)d_in[6];
    const float* wf = (const float*)d_in[7];
    const float* bf = (const float*)d_in[8];
    const float* wm = (const float*)d_in[9];
    const float* bm = (const float*)d_in[10];
    float* out = (float*)d_out;

    cudaFuncSetAttribute(fused_kernel,
                         cudaFuncAttributeMaxDynamicSharedMemorySize, SMEMB);

    geom_kernel<<<128, 256>>>();
    pad_kernel<<<1544, 256>>>();
    wtprep_kernel<<<144, 256>>>(wf);
    nchw2xp_kernel<<<4096, 256>>>(m);
    gather_kernel<<<4096, 256>>>(bb, d, f, l, r, u);
    fused_kernel<<<512, 256, SMEMB>>>(m, bf, wm, bm, out);
}

// round 5
// speedup vs baseline: 3.2668x; 2.0181x over previous
#include <cuda_runtime.h>
#include <cuda_fp16.h>
#include <cstdint>

#define H   128
#define W   256
#define HW  32768
#define FH  128
#define XPH 130
#define XPW 258
#define PLANE (XPH*XPW*32)

// ---------------- scratch (device globals; no allocation allowed) ----------------
__device__ __half g_xm_h[8*PLANE];   // m, padded NHWC (2x 32ch planes per batch), fp16
__device__ __half g_xa_h[8*PLANE];   // aux, same layout
__device__ __half g_wt_h[18*2048];   // weights [chunk(icc,tap)][oc64][ic32], fp16
__device__ int   g_geo[HW];
__device__ float g_dx[HW];
__device__ float g_dy[HW];

// ---------------- helpers ----------------
__device__ __forceinline__ uint32_t smem_u32(const void* p) {
    uint32_t a;
    asm("{ .reg .u64 t; cvta.to.shared.u64 t, %1; cvt.u32.u64 %0, t; }" : "=r"(a) : "l"(p));
    return a;
}
__device__ __forceinline__ void cp16(uint32_t dst, const void* src) {
    unsigned long long g = (unsigned long long)__cvta_generic_to_global(src);
    asm volatile("cp.async.cg.shared.global [%0], [%1], 16;" :: "r"(dst), "l"(g) : "memory");
}
__device__ __forceinline__ void mma16(float* d, const uint32_t* a, const uint32_t* b) {
    asm volatile(
        "mma.sync.aligned.m16n8k16.row.col.f32.f16.f16.f32 "
        "{%0,%1,%2,%3}, {%4,%5,%6,%7}, {%8,%9}, {%0,%1,%2,%3};"
        : "+f"(d[0]), "+f"(d[1]), "+f"(d[2]), "+f"(d[3])
        : "r"(a[0]), "r"(a[1]), "r"(a[2]), "r"(a[3]), "r"(b[0]), "r"(b[1]));
}

// ---------------- 1) per-pixel cube geometry ----------------
__global__ void geom_kernel() {
    int p = blockIdx.x * blockDim.x + threadIdx.x;
    if (p >= HW) return;
    int i = p >> 8;
    int j = p & 255;
    const float PI = 3.14159265358979323846f;
    float lat = (0.5f - (i + 0.5f) / 128.f) * PI;
    float lon = (2.f * (j + 0.5f) / 256.f - 1.f) * PI;
    float cl = cosf(lat);
    float vx = cl * sinf(lon);
    float vy = sinf(lat);
    float vz = cl * cosf(lon);
    float ax = fabsf(vx), ay = fabsf(vy), az = fabsf(vz);
    bool cond_z = (az >= ax) && (az >= ay);
    bool cond_x = (!cond_z) && (ax >= ay);
    int face;
    if (cond_z)      face = (vz > 0.f) ? 2 : 0;
    else if (cond_x) face = (vx > 0.f) ? 4 : 3;
    else             face = (vy > 0.f) ? 5 : 1;
    float den, a, bc;
    switch (face) {
        case 0: den = -vz; a = -vx / den; bc =  vy / den; break;
        case 1: den = -vy; a =  vx / den; bc = -vz / den; break;
        case 2: den =  vz; a =  vx / den; bc =  vy / den; break;
        case 3: den = -vx; a =  vz / den; bc =  vy / den; break;
        case 4: den =  vx; a = -vz / den; bc =  vy / den; break;
        default:den =  vy; a =  vx / den; bc =  vz / den; break;
    }
    float uu = fminf(fmaxf((a   + 1.f) * 0.5f * 127.f, 0.f), 127.f);
    float vv = fminf(fmaxf((1.f - bc ) * 0.5f * 127.f, 0.f), 127.f);
    int x0 = (int)floorf(uu);
    int y0 = (int)floorf(vv);
    int x1 = min(x0 + 1, 127);
    int y1 = min(y0 + 1, 127);
    g_geo[p] = face | (x0 << 3) | (y0 << 10) | (x1 << 17) | (y1 << 24);
    g_dx[p] = uu - (float)x0;
    g_dy[p] = vv - (float)y0;
}

// ---------------- 2) zero padded borders (fp16) ----------------
__global__ void pad_kernel() {
    const int PER = 24704;
    int t = blockIdx.x * 256 + threadIdx.x;
    if (t >= 2 * 8 * PER) return;
    __half* base = (t < 8 * PER) ? g_xm_h : g_xa_h;
    int r = t % (8 * PER);
    int plane = r / PER;
    int e = r % PER;
    int y, x, ic;
    if (e < 16512) {
        y = (e < 8256) ? 0 : 129;
        int o = e % 8256; x = o >> 5; ic = o & 31;
    } else {
        int e2 = e - 16512;
        x = (e2 < 4096) ? 0 : 257;
        int o = e2 & 4095; y = 1 + (o >> 5); ic = o & 31;
    }
    base[((size_t)(plane * XPH + y) * XPW + x) * 32 + ic] = __float2half(0.f);
}

// ---------------- 3) weights -> [chunk][oc][ic32] fp16 ----------------
__global__ void wtprep_kernel(const float* __restrict__ wf) {
    int idx = blockIdx.x * 256 + threadIdx.x;
    if (idx >= 18 * 2048) return;
    int ch = idx >> 11, rr = idx & 2047;
    int oc = rr >> 5, ic = rr & 31;
    int icc = ch / 9, kk = ch % 9;
    g_wt_h[idx] = __float2half(wf[(oc * 64 + icc * 32 + ic) * 9 + kk]);
}

// ---------------- 4) m: NCHW -> padded NHWC fp16 ----------------
__global__ __launch_bounds__(256) void nchw2xp_kernel(const float* __restrict__ m) {
    __shared__ float sm[64][33];
    int blk = blockIdx.x;                        // b*1024 + y*8 + xt
    int xt = blk & 7, y = (blk >> 3) & 127, b = blk >> 10;
    int tid = threadIdx.x;
    int xl = tid & 31, cw = tid >> 5;
    #pragma unroll
    for (int k = 0; k < 8; k++) {
        int c = cw + k * 8;
        sm[c][xl] = m[(((size_t)(b * 64 + c)) * 128 + y) * 256 + xt * 32 + xl];
    }
    __syncthreads();
    for (int i = tid; i < 2048; i += 256) {
        int px = i >> 6, c = i & 63, icc = c >> 5;
        g_xm_h[(((size_t)((b * 2 + icc) * XPH) + y + 1) * XPW + xt * 32 + px + 1) * 32 + (c & 31)]
            = __float2half(sm[c][px]);
    }
}

// ---------------- 5) bilinear cube gather -> padded NHWC aux fp16 ----------------
__global__ __launch_bounds__(256) void gather_kernel(
    const float* __restrict__ fb, const float* __restrict__ fd,
    const float* __restrict__ ff, const float* __restrict__ fl,
    const float* __restrict__ fr, const float* __restrict__ fu)
{
    __shared__ float sm[64][33];
    int blk = blockIdx.x;
    int xt = blk & 7, y = (blk >> 3) & 127, b = blk >> 10;
    int tid = threadIdx.x;
    int xl = tid & 31, cw = tid >> 5;
    int p = y * 256 + xt * 32 + xl;
    int geo = g_geo[p];
    int face = geo & 7;
    int x0 = (geo >> 3) & 127, y0 = (geo >> 10) & 127;
    int x1 = (geo >> 17) & 127, y1 = (geo >> 24) & 127;
    float dx = g_dx[p], dy = g_dy[p];
    float w00 = (1.f - dx) * (1.f - dy), w01 = dx * (1.f - dy);
    float w10 = (1.f - dx) * dy,         w11 = dx * dy;
    const float* fp0;
    switch (face) {
        case 0: fp0 = fb; break; case 1: fp0 = fd; break; case 2: fp0 = ff; break;
        case 3: fp0 = fl; break; case 4: fp0 = fr; break; default: fp0 = fu; break;
    }
    #pragma unroll
    for (int k = 0; k < 8; k++) {
        int c = cw + k * 8;
        const float* fp = fp0 + ((size_t)(b * 64 + c)) * (FH * FH);
        sm[c][xl] = fp[y0 * FH + x0] * w00 + fp[y0 * FH + x1] * w01
                  + fp[y1 * FH + x0] * w10 + fp[y1 * FH + x1] * w11;
    }
    __syncthreads();
    for (int i = tid; i < 2048; i += 256) {
        int px = i >> 6, c = i & 63, icc = c >> 5;
        g_xa_h[(((size_t)((b * 2 + icc) * XPH) + y + 1) * XPW + xt * 32 + px + 1) * 32 + (c & 31)]
            = __float2half(sm[c][px]);
    }
}

// ---------------- 6) fused: both convs (mma fp16 k16) + mask + blend ----------------
// smem bytes: [0,10240) wt bufs (2 x 64 rows x 80B)
//             [10240,92160) px bufs (2 bufs x 2 slabs x 256 x 80B)
//             [92160) bias 64f; [92416) wm 128f; [92928) bm; [92944) maskS 256f
// epilogue: stage [256][65] f32 reuses px area at 10240 (66560B)
#define SB_WT  0
#define SB_PX  10240
#define SB_PAR 92160
#define SMEMB  94208

__global__ __launch_bounds__(512, 1) void fused_kernel(
    const float* __restrict__ m_in, const float* __restrict__ bfu,
    const float* __restrict__ wm,   const float* __restrict__ bm,
    float* __restrict__ out)
{
    extern __shared__ char smc[];
    float* sf = (float*)smc;
    const uint32_t sb = smem_u32(smc);
    const int tid = threadIdx.x;
    const int wid = tid >> 5;
    const int lane = tid & 31;
    const int r4 = lane >> 2, c4 = lane & 3;
    const int b = blockIdx.x >> 7;
    const int y = blockIdx.x & 127;

    float* sbias = (float*)(smc + SB_PAR);
    float* swm   = (float*)(smc + SB_PAR + 256);
    float* sbm   = (float*)(smc + SB_PAR + 768);
    float* maskS = (float*)(smc + SB_PAR + 784);
    if (tid < 64)  sbias[tid] = bfu[tid];
    if (tid < 128) swm[tid]   = wm[tid];
    if (tid == 0)  sbm[0]     = bm[0];

    float acc[2][8][4];                          // [conv][nt][frag]
    #pragma unroll
    for (int v = 0; v < 2; v++)
        #pragma unroll
        for (int nt = 0; nt < 8; nt++)
            #pragma unroll
            for (int e = 0; e < 4; e++) acc[v][nt][e] = 0.f;

    auto fill = [&](int c) {
        int icc = c / 9, kk = c % 9, ky = kk / 3, kx = kk % 3;
        size_t rowoff = (((size_t)((b * 2 + icc) * XPH + y + ky)) * XPW + kx) * 32;
        const __half* srcm = g_xm_h + rowoff;
        const __half* srca = g_xa_h + rowoff;
        uint32_t dpx = sb + SB_PX + (c & 1) * 40960;
        #pragma unroll
        for (int i = 0; i < 4; i++) {
            int j = tid + i * 512;               // 2048 cp16: 2 slabs x 1024
            int slab = j >> 10;
            int jj = j & 1023;
            int px = jj >> 2, q = jj & 3;
            const __half* s = (slab ? srca : srcm) + px * 32 + q * 8;
            cp16(dpx + slab * 20480 + px * 80 + q * 16, s);
        }
        if (tid < 256) {
            int oc = tid >> 2, q = tid & 3;
            cp16(sb + SB_WT + (c & 1) * 5120 + oc * 80 + q * 16,
                 g_wt_h + c * 2048 + oc * 32 + q * 8);
        }
    };

    fill(0);
    asm volatile("cp.async.commit_group;" ::: "memory");

    const int px0 = wid * 16 + r4;               // this thread's A rows: px0, px0+8
    for (int c = 0; c < 18; c++) {
        __syncthreads();
        if (c < 17) fill(c + 1);
        asm volatile("cp.async.commit_group;" ::: "memory");
        if (c < 17) asm volatile("cp.async.wait_group 1;" ::: "memory");
        else        asm volatile("cp.async.wait_group 0;" ::: "memory");
        __syncthreads();

        const uint32_t wtb = sb + SB_WT + (c & 1) * 5120;
        const uint32_t pxb = sb + SB_PX + (c & 1) * 40960;

        #pragma unroll
        for (int ks = 0; ks < 2; ks++) {
            const uint32_t col = (ks * 8 + c4) * 4;    // byte offset of k-word
            uint32_t bw[8][2];
            #pragma unroll
            for (int nt = 0; nt < 8; nt++) {
                uint32_t a0 = wtb + (nt * 8 + r4) * 80 + col;
                asm volatile("ld.shared.u32 %0, [%1];"      : "=r"(bw[nt][0]) : "r"(a0));
                asm volatile("ld.shared.u32 %0, [%1];"      : "=r"(bw[nt][1]) : "r"(a0 + 16));
            }
            uint32_t am[4], aa[4];
            {
                uint32_t a0 = pxb + px0 * 80 + col;
                asm volatile("ld.shared.u32 %0, [%1];" : "=r"(am[0]) : "r"(a0));
                asm volatile("ld.shared.u32 %0, [%1];" : "=r"(am[1]) : "r"(a0 + 640));
                asm volatile("ld.shared.u32 %0, [%1];" : "=r"(am[2]) : "r"(a0 + 16));
                asm volatile("ld.shared.u32 %0, [%1];" : "=r"(am[3]) : "r"(a0 + 656));
                uint32_t a1 = a0 + 20480;
                asm volatile("ld.shared.u32 %0, [%1];" : "=r"(aa[0]) : "r"(a1));
                asm volatile("ld.shared.u32 %0, [%1];" : "=r"(aa[1]) : "r"(a1 + 640));
                asm volatile("ld.shared.u32 %0, [%1];" : "=r"(aa[2]) : "r"(a1 + 16));
                asm volatile("ld.shared.u32 %0, [%1];" : "=r"(aa[3]) : "r"(a1 + 656));
            }
            #pragma unroll
            for (int nt = 0; nt < 8; nt++) {
                mma16(acc[0][nt], am, bw[nt]);
                mma16(acc[1][nt], aa, bw[nt]);
            }
        }
    }

    __syncthreads();                             // all MMA smem reads done before stage reuse

    // ---------------- epilogue ----------------
    float* stage = (float*)(smc + SB_PX);        // [256][65] relu(aux)
    const float bmv = sbm[0];

    float tot[2];
    #pragma unroll
    for (int h = 0; h < 2; h++) {
        float s = 0.f;
        int px = px0 + 8 * h;
        #pragma unroll
        for (int nt = 0; nt < 8; nt++)
            #pragma unroll
            for (int j = 0; j < 2; j++) {
                int oc = nt * 8 + 2 * c4 + j;
                float bv = sbias[oc];
                float vm = fmaxf(acc[0][nt][2 * h + j] + bv, 0.f);
                float va = fmaxf(acc[1][nt][2 * h + j] + bv, 0.f);
                s += swm[oc] * vm + swm[64 + oc] * va;
                stage[px * 65 + oc] = va;
            }
        tot[h] = s;
    }
    #pragma unroll
    for (int h = 0; h < 2; h++) {
        float s = tot[h];
        s += __shfl_xor_sync(0xffffffffu, s, 1);
        s += __shfl_xor_sync(0xffffffffu, s, 2);
        if (c4 == 0)
            maskS[px0 + 8 * h] = 1.f / (1.f + expf(-(s + bmv)));
    }
    __syncthreads();

    {
        int px = tid & 255;
        int ocg = tid >> 8;                      // 0 or 1 -> oc 0..31 / 32..63
        float mk = maskS[px];
        #pragma unroll 8
        for (int k = 0; k < 32; k++) {
            int oc = ocg * 32 + k;
            size_t idx = (((size_t)(b * 64 + oc)) * 128 + y) * 256 + px;
            out[idx] = m_in[idx] + mk * stage[px * 65 + oc];
        }
    }
}

// ---------------- launch ----------------
extern "C" void kernel_launch(void* const* d_in, const int* in_sizes, int n_in,
                              void* d_out, int out_size)
{
    const float* m  = (const float*)d_in[0];
    const float* f  = (const float*)d_in[1];
    const float* r  = (const float*)d_in[2];
    const float* bb = (const float*)d_in[3];
    const float* l  = (const float*)d_in[4];
    const float* u  = (const float*)d_in[5];
    const float* d  = (const float*)d_in[6];
    const float* wf = (const float*)d_in[7];
    const float* bf = (const float*)d_in[8];
    const float* wm = (const float*)d_in[9];
    const float* bm = (const float*)d_in[10];
    float* out = (float*)d_out;

    cudaFuncSetAttribute(fused_kernel,
                         cudaFuncAttributeMaxDynamicSharedMemorySize, SMEMB);

    geom_kernel<<<128, 256>>>();
    pad_kernel<<<1544, 256>>>();
    wtprep_kernel<<<144, 256>>>(wf);
    nchw2xp_kernel<<<4096, 256>>>(m);
    gather_kernel<<<4096, 256>>>(bb, d, f, l, r, u);
    fused_kernel<<<512, 512, SMEMB>>>(m, bf, wm, bm, out);
}

// round 6
// speedup vs baseline: 4.1591x; 1.2731x over previous
#include <cuda_runtime.h>
#include <cuda_fp16.h>
#include <cstdint>

#define H   128
#define W   256
#define HW  32768
#define FH  128
#define XPH 130
#define XPW 258
#define PLANE (XPH*XPW*32)

// ---------------- scratch (device globals; no allocation allowed) ----------------
__device__ __half g_xm_h[8*PLANE];   // m, padded NHWC (2x 32ch planes per batch), fp16
__device__ __half g_xa_h[8*PLANE];   // aux, same layout
__device__ __half g_wt_h[18*2048];   // weights [chunk(icc,tap)][oc64][ic32], fp16
__device__ int   g_geo[HW];
__device__ float g_dx[HW];
__device__ float g_dy[HW];

// ---------------- helpers ----------------
__device__ __forceinline__ uint32_t smem_u32(const void* p) {
    uint32_t a;
    asm("{ .reg .u64 t; cvta.to.shared.u64 t, %1; cvt.u32.u64 %0, t; }" : "=r"(a) : "l"(p));
    return a;
}
__device__ __forceinline__ void cp16(uint32_t dst, const void* src) {
    unsigned long long g = (unsigned long long)__cvta_generic_to_global(src);
    asm volatile("cp.async.cg.shared.global [%0], [%1], 16;" :: "r"(dst), "l"(g) : "memory");
}
__device__ __forceinline__ void ldm4(uint32_t* r, uint32_t addr) {
    asm volatile("ldmatrix.sync.aligned.m8n8.x4.shared.b16 {%0,%1,%2,%3}, [%4];"
        : "=r"(r[0]), "=r"(r[1]), "=r"(r[2]), "=r"(r[3]) : "r"(addr));
}
__device__ __forceinline__ void mma16(float* d, const uint32_t* a, const uint32_t* b) {
    asm volatile(
        "mma.sync.aligned.m16n8k16.row.col.f32.f16.f16.f32 "
        "{%0,%1,%2,%3}, {%4,%5,%6,%7}, {%8,%9}, {%0,%1,%2,%3};"
        : "+f"(d[0]), "+f"(d[1]), "+f"(d[2]), "+f"(d[3])
        : "r"(a[0]), "r"(a[1]), "r"(a[2]), "r"(a[3]), "r"(b[0]), "r"(b[1]));
}

// ---------------- 1) per-pixel cube geometry ----------------
__global__ void geom_kernel() {
    int p = blockIdx.x * blockDim.x + threadIdx.x;
    if (p >= HW) return;
    int i = p >> 8;
    int j = p & 255;
    const float PI = 3.14159265358979323846f;
    float lat = (0.5f - (i + 0.5f) / 128.f) * PI;
    float lon = (2.f * (j + 0.5f) / 256.f - 1.f) * PI;
    float cl = cosf(lat);
    float vx = cl * sinf(lon);
    float vy = sinf(lat);
    float vz = cl * cosf(lon);
    float ax = fabsf(vx), ay = fabsf(vy), az = fabsf(vz);
    bool cond_z = (az >= ax) && (az >= ay);
    bool cond_x = (!cond_z) && (ax >= ay);
    int face;
    if (cond_z)      face = (vz > 0.f) ? 2 : 0;
    else if (cond_x) face = (vx > 0.f) ? 4 : 3;
    else             face = (vy > 0.f) ? 5 : 1;
    float den, a, bc;
    switch (face) {
        case 0: den = -vz; a = -vx / den; bc =  vy / den; break;
        case 1: den = -vy; a =  vx / den; bc = -vz / den; break;
        case 2: den =  vz; a =  vx / den; bc =  vy / den; break;
        case 3: den = -vx; a =  vz / den; bc =  vy / den; break;
        case 4: den =  vx; a = -vz / den; bc =  vy / den; break;
        default:den =  vy; a =  vx / den; bc =  vz / den; break;
    }
    float uu = fminf(fmaxf((a   + 1.f) * 0.5f * 127.f, 0.f), 127.f);
    float vv = fminf(fmaxf((1.f - bc ) * 0.5f * 127.f, 0.f), 127.f);
    int x0 = (int)floorf(uu);
    int y0 = (int)floorf(vv);
    int x1 = min(x0 + 1, 127);
    int y1 = min(y0 + 1, 127);
    g_geo[p] = face | (x0 << 3) | (y0 << 10) | (x1 << 17) | (y1 << 24);
    g_dx[p] = uu - (float)x0;
    g_dy[p] = vv - (float)y0;
}

// ---------------- 2) zero padded borders (fp16) ----------------
__global__ void pad_kernel() {
    const int PER = 24704;
    int t = blockIdx.x * 256 + threadIdx.x;
    if (t >= 2 * 8 * PER) return;
    __half* base = (t < 8 * PER) ? g_xm_h : g_xa_h;
    int r = t % (8 * PER);
    int plane = r / PER;
    int e = r % PER;
    int y, x, ic;
    if (e < 16512) {
        y = (e < 8256) ? 0 : 129;
        int o = e % 8256; x = o >> 5; ic = o & 31;
    } else {
        int e2 = e - 16512;
        x = (e2 < 4096) ? 0 : 257;
        int o = e2 & 4095; y = 1 + (o >> 5); ic = o & 31;
    }
    base[((size_t)(plane * XPH + y) * XPW + x) * 32 + ic] = __float2half(0.f);
}

// ---------------- 3) weights -> [chunk][oc][ic32] fp16 ----------------
__global__ void wtprep_kernel(const float* __restrict__ wf) {
    int idx = blockIdx.x * 256 + threadIdx.x;
    if (idx >= 18 * 2048) return;
    int ch = idx >> 11, rr = idx & 2047;
    int oc = rr >> 5, ic = rr & 31;
    int icc = ch / 9, kk = ch % 9;
    g_wt_h[idx] = __float2half(wf[(oc * 64 + icc * 32 + ic) * 9 + kk]);
}

// ---------------- 4) m: NCHW -> padded NHWC fp16 ----------------
__global__ __launch_bounds__(256) void nchw2xp_kernel(const float* __restrict__ m) {
    __shared__ float sm[64][33];
    int blk = blockIdx.x;                        // b*1024 + y*8 + xt
    int xt = blk & 7, y = (blk >> 3) & 127, b = blk >> 10;
    int tid = threadIdx.x;
    int xl = tid & 31, cw = tid >> 5;
    #pragma unroll
    for (int k = 0; k < 8; k++) {
        int c = cw + k * 8;
        sm[c][xl] = m[(((size_t)(b * 64 + c)) * 128 + y) * 256 + xt * 32 + xl];
    }
    __syncthreads();
    for (int i = tid; i < 2048; i += 256) {
        int px = i >> 6, c = i & 63, icc = c >> 5;
        g_xm_h[(((size_t)((b * 2 + icc) * XPH) + y + 1) * XPW + xt * 32 + px + 1) * 32 + (c & 31)]
            = __float2half(sm[c][px]);
    }
}

// ---------------- 5) bilinear cube gather -> padded NHWC aux fp16 ----------------
__global__ __launch_bounds__(256) void gather_kernel(
    const float* __restrict__ fb, const float* __restrict__ fd,
    const float* __restrict__ ff, const float* __restrict__ fl,
    const float* __restrict__ fr, const float* __restrict__ fu)
{
    __shared__ float sm[64][33];
    int blk = blockIdx.x;
    int xt = blk & 7, y = (blk >> 3) & 127, b = blk >> 10;
    int tid = threadIdx.x;
    int xl = tid & 31, cw = tid >> 5;
    int p = y * 256 + xt * 32 + xl;
    int geo = g_geo[p];
    int face = geo & 7;
    int x0 = (geo >> 3) & 127, y0 = (geo >> 10) & 127;
    int x1 = (geo >> 17) & 127, y1 = (geo >> 24) & 127;
    float dx = g_dx[p], dy = g_dy[p];
    float w00 = (1.f - dx) * (1.f - dy), w01 = dx * (1.f - dy);
    float w10 = (1.f - dx) * dy,         w11 = dx * dy;
    const float* fp0;
    switch (face) {
        case 0: fp0 = fb; break; case 1: fp0 = fd; break; case 2: fp0 = ff; break;
        case 3: fp0 = fl; break; case 4: fp0 = fr; break; default: fp0 = fu; break;
    }
    #pragma unroll
    for (int k = 0; k < 8; k++) {
        int c = cw + k * 8;
        const float* fp = fp0 + ((size_t)(b * 64 + c)) * (FH * FH);
        sm[c][xl] = fp[y0 * FH + x0] * w00 + fp[y0 * FH + x1] * w01
                  + fp[y1 * FH + x0] * w10 + fp[y1 * FH + x1] * w11;
    }
    __syncthreads();
    for (int i = tid; i < 2048; i += 256) {
        int px = i >> 6, c = i & 63, icc = c >> 5;
        g_xa_h[(((size_t)((b * 2 + icc) * XPH) + y + 1) * XPW + xt * 32 + px + 1) * 32 + (c & 31)]
            = __float2half(sm[c][px]);
    }
}

// ---------------- 6) fused: both convs (mma fp16 k16, row-buffered) + mask + blend ----------------
// smem bytes:
//   [0, 92160)          18 weight chunks, 64 oc rows x 80B each (5120B/chunk)
//   [92160, 174720)     row bufs: 2 bufs x 2 slabs x 258 px x 80B (20640B/slab)
//   [174720, ...)       bias 64f, wm 128f, bm 1f, maskS 256f
//   epilogue reuse: stage [256][65] f32 at 92160
#define SB_WT  0
#define SB_ROW 92160
#define SB_PAR 174720
#define SMEMB  176640

__global__ __launch_bounds__(512, 1) void fused_kernel(
    const float* __restrict__ m_in, const float* __restrict__ bfu,
    const float* __restrict__ wm,   const float* __restrict__ bm,
    float* __restrict__ out)
{
    extern __shared__ char smc[];
    const uint32_t sb = smem_u32(smc);
    const int tid = threadIdx.x;
    const int wid = tid >> 5;
    const int lane = tid & 31;
    const int r4 = lane >> 2, c4 = lane & 3;
    const int b = blockIdx.x >> 7;
    const int y = blockIdx.x & 127;

    float* sbias = (float*)(smc + SB_PAR);
    float* swm   = (float*)(smc + SB_PAR + 256);
    float* sbm   = (float*)(smc + SB_PAR + 768);
    float* maskS = (float*)(smc + SB_PAR + 784);
    if (tid < 64)  sbias[tid] = bfu[tid];
    if (tid < 128) swm[tid]   = wm[tid];
    if (tid == 0)  sbm[0]     = bm[0];

    float acc[2][8][4];                          // [conv][nt][frag]
    #pragma unroll
    for (int v = 0; v < 2; v++)
        #pragma unroll
        for (int nt = 0; nt < 8; nt++)
            #pragma unroll
            for (int e = 0; e < 4; e++) acc[v][nt][e] = 0.f;

    // weights: all 18 chunks, once (4608 cp16)
    for (int j = tid; j < 4608; j += 512) {
        int ch = j >> 8, rr = j & 255, oc = rr >> 2, q = rr & 3;
        cp16(sb + SB_WT + ch * 5120 + oc * 80 + q * 16,
             g_wt_h + ch * 2048 + oc * 32 + q * 8);
    }

    // row fill: stage s -> (icc = s/3, ky = s%3), both slabs, full padded row
    auto fillrow = [&](int s) {
        int icc = s / 3, ky = s % 3;
        size_t rowoff = ((size_t)((b * 2 + icc) * XPH + y + ky)) * XPW * 32;
        const __half* rm = g_xm_h + rowoff;
        const __half* ra = g_xa_h + rowoff;
        uint32_t dst = sb + SB_ROW + (s & 1) * 41280;
        #pragma unroll
        for (int i = 0; i < 5; i++) {
            int j = tid + i * 512;
            if (j < 2064) {                      // 2 slabs x 258 px x 4 cp16
                int slab = (j >= 1032);
                int jj = j - slab * 1032;
                int px = jj >> 2, q = jj & 3;
                cp16(dst + slab * 20640 + px * 80 + q * 16,
                     (slab ? ra : rm) + px * 32 + q * 8);
            }
        }
    };

    fillrow(0);
    asm volatile("cp.async.commit_group;" ::: "memory");

    const int mq = lane >> 3, r8 = lane & 7;     // ldmatrix lane roles
    for (int s = 0; s < 6; s++) {
        __syncthreads();                         // prior stage's smem reads done
        if (s < 5) fillrow(s + 1);
        asm volatile("cp.async.commit_group;" ::: "memory");
        if (s < 5) asm volatile("cp.async.wait_group 1;" ::: "memory");
        else       asm volatile("cp.async.wait_group 0;" ::: "memory");
        __syncthreads();

        const uint32_t rowb = sb + SB_ROW + (s & 1) * 41280;
        const int icc = s / 3, ky = s % 3;
        const uint32_t wtb0 = sb + SB_WT + (icc * 9 + ky * 3) * 5120;

        #pragma unroll
        for (int kx = 0; kx < 3; kx++) {
            const uint32_t wtb = wtb0 + kx * 5120;
            #pragma unroll
            for (int ks = 0; ks < 2; ks++) {
                // B: 4x ldmatrix.x4, nt-pairs; lane ptr: matrix mq covers
                //    {nt=2p k0-7, nt=2p k8-15, nt=2p+1 k0-7, nt=2p+1 k8-15}
                uint32_t bw[8][2];
                #pragma unroll
                for (int p = 0; p < 4; p++) {
                    uint32_t tmp[4];
                    uint32_t addr = wtb + ((p * 2 + (mq >> 1)) * 8 + r8) * 80
                                  + (mq & 1) * 16 + ks * 32;
                    ldm4(tmp, addr);
                    bw[2 * p][0] = tmp[0]; bw[2 * p][1] = tmp[1];
                    bw[2 * p + 1][0] = tmp[2]; bw[2 * p + 1][1] = tmp[3];
                }
                // A: rows = px (wid*16 + 0..15) shifted by kx
                uint32_t am[4], aa[4];
                uint32_t aaddr = rowb + (wid * 16 + (mq & 1) * 8 + r8 + kx) * 80
                               + (mq >> 1) * 16 + ks * 32;
                ldm4(am, aaddr);
                ldm4(aa, aaddr + 20640);
                #pragma unroll
                for (int nt = 0; nt < 8; nt++) {
                    mma16(acc[0][nt], am, bw[nt]);
                    mma16(acc[1][nt], aa, bw[nt]);
                }
            }
        }
    }

    __syncthreads();                             // all MMA smem reads done before stage reuse

    // ---------------- epilogue ----------------
    float* stage = (float*)(smc + SB_ROW);       // [256][65] relu(aux)
    const float bmv = sbm[0];
    const int px0 = wid * 16 + r4;

    float tot[2];
    #pragma unroll
    for (int h = 0; h < 2; h++) {
        float s = 0.f;
        int px = px0 + 8 * h;
        #pragma unroll
        for (int nt = 0; nt < 8; nt++)
            #pragma unroll
            for (int j = 0; j < 2; j++) {
                int oc = nt * 8 + 2 * c4 + j;
                float bv = sbias[oc];
                float vm = fmaxf(acc[0][nt][2 * h + j] + bv, 0.f);
                float va = fmaxf(acc[1][nt][2 * h + j] + bv, 0.f);
                s += swm[oc] * vm + swm[64 + oc] * va;
                stage[px * 65 + oc] = va;
            }
        tot[h] = s;
    }
    #pragma unroll
    for (int h = 0; h < 2; h++) {
        float s = tot[h];
        s += __shfl_xor_sync(0xffffffffu, s, 1);
        s += __shfl_xor_sync(0xffffffffu, s, 2);
        if (c4 == 0)
            maskS[px0 + 8 * h] = 1.f / (1.f + expf(-(s + bmv)));
    }
    __syncthreads();

    {
        int px = tid & 255;
        int ocg = tid >> 8;                      // 0 or 1 -> oc 0..31 / 32..63
        float mk = maskS[px];
        #pragma unroll 8
        for (int k = 0; k < 32; k++) {
            int oc = ocg * 32 + k;
            size_t idx = (((size_t)(b * 64 + oc)) * 128 + y) * 256 + px;
            out[idx] = m_in[idx] + mk * stage[px * 65 + oc];
        }
    }
}

// ---------------- launch ----------------
extern "C" void kernel_launch(void* const* d_in, const int* in_sizes, int n_in,
                              void* d_out, int out_size)
{
    const float* m  = (const float*)d_in[0];
    const float* f  = (const float*)d_in[1];
    const float* r  = (const float*)d_in[2];
    const float* bb = (const float*)d_in[3];
    const float* l  = (const float*)d_in[4];
    const float* u  = (const float*)d_in[5];
    const float* d  = (const float*)d_in[6];
    const float* wf = (const float*)d_in[7];
    const float* bf = (const float*)d_in[8];
    const float* wm = (const float*)d_in[9];
    const float* bm = (const float*)d_in[10];
    float* out = (float*)d_out;

    cudaFuncSetAttribute(fused_kernel,
                         cudaFuncAttributeMaxDynamicSharedMemorySize, SMEMB);

    geom_kernel<<<128, 256>>>();
    pad_kernel<<<1544, 256>>>();
    wtprep_kernel<<<144, 256>>>(wf);
    nchw2xp_kernel<<<4096, 256>>>(m);
    gather_kernel<<<4096, 256>>>(bb, d, f, l, r, u);
    fused_kernel<<<512, 512, SMEMB>>>(m, bf, wm, bm, out);
}

// round 8
// speedup vs baseline: 4.5064x; 1.0835x over previous
#include <cuda_runtime.h>
#include <cuda_fp16.h>
#include <cstdint>

#define H   128
#define W   256
#define HW  32768
#define FH  128
#define XPH 130
#define XPW 258
#define PLANE (XPH*XPW*32)

// ---------------- scratch (device globals; no allocation allowed) ----------------
__device__ __half g_xm_h[8*PLANE];   // m, padded NHWC (2x 32ch planes per batch), fp16
__device__ __half g_xa_h[8*PLANE];   // aux, same layout
__device__ __half g_wt_h[18*2048];   // weights [chunk(icc,tap)][oc64][ic32], fp16
__device__ int   g_geo[HW];
__device__ float g_dx[HW];
__device__ float g_dy[HW];

// ---------------- helpers ----------------
__device__ __forceinline__ uint32_t smem_u32(const void* p) {
    uint32_t a;
    asm("{ .reg .u64 t; cvta.to.shared.u64 t, %1; cvt.u32.u64 %0, t; }" : "=r"(a) : "l"(p));
    return a;
}
__device__ __forceinline__ uint32_t h2u(__half2 h) {
    return *reinterpret_cast<uint32_t*>(&h);
}
__device__ __forceinline__ void cp16(uint32_t dst, const void* src) {
    unsigned long long g = (unsigned long long)__cvta_generic_to_global(src);
    asm volatile("cp.async.cg.shared.global [%0], [%1], 16;" :: "r"(dst), "l"(g) : "memory");
}
__device__ __forceinline__ void ldm4(uint32_t* r, uint32_t addr) {
    asm volatile("ldmatrix.sync.aligned.m8n8.x4.shared.b16 {%0,%1,%2,%3}, [%4];"
        : "=r"(r[0]), "=r"(r[1]), "=r"(r[2]), "=r"(r[3]) : "r"(addr));
}
__device__ __forceinline__ void mma16(float* d, const uint32_t* a, const uint32_t* b) {
    asm volatile(
        "mma.sync.aligned.m16n8k16.row.col.f32.f16.f16.f32 "
        "{%0,%1,%2,%3}, {%4,%5,%6,%7}, {%8,%9}, {%0,%1,%2,%3};"
        : "+f"(d[0]), "+f"(d[1]), "+f"(d[2]), "+f"(d[3])
        : "r"(a[0]), "r"(a[1]), "r"(a[2]), "r"(a[3]), "r"(b[0]), "r"(b[1]));
}

// ---------------- 1) per-pixel cube geometry ----------------
__global__ void geom_kernel() {
    int p = blockIdx.x * blockDim.x + threadIdx.x;
    if (p >= HW) return;
    int i = p >> 8;
    int j = p & 255;
    const float PI = 3.14159265358979323846f;
    float lat = (0.5f - (i + 0.5f) / 128.f) * PI;
    float lon = (2.f * (j + 0.5f) / 256.f - 1.f) * PI;
    float cl = cosf(lat);
    float vx = cl * sinf(lon);
    float vy = sinf(lat);
    float vz = cl * cosf(lon);
    float ax = fabsf(vx), ay = fabsf(vy), az = fabsf(vz);
    bool cond_z = (az >= ax) && (az >= ay);
    bool cond_x = (!cond_z) && (ax >= ay);
    int face;
    if (cond_z)      face = (vz > 0.f) ? 2 : 0;
    else if (cond_x) face = (vx > 0.f) ? 4 : 3;
    else             face = (vy > 0.f) ? 5 : 1;
    float den, a, bc;
    switch (face) {
        case 0: den = -vz; a = -vx / den; bc =  vy / den; break;
        case 1: den = -vy; a =  vx / den; bc = -vz / den; break;
        case 2: den =  vz; a =  vx / den; bc =  vy / den; break;
        case 3: den = -vx; a =  vz / den; bc =  vy / den; break;
        case 4: den =  vx; a = -vz / den; bc =  vy / den; break;
        default:den =  vy; a =  vx / den; bc =  vz / den; break;
    }
    float uu = fminf(fmaxf((a   + 1.f) * 0.5f * 127.f, 0.f), 127.f);
    float vv = fminf(fmaxf((1.f - bc ) * 0.5f * 127.f, 0.f), 127.f);
    int x0 = (int)floorf(uu);
    int y0 = (int)floorf(vv);
    int x1 = min(x0 + 1, 127);
    int y1 = min(y0 + 1, 127);
    g_geo[p] = face | (x0 << 3) | (y0 << 10) | (x1 << 17) | (y1 << 24);
    g_dx[p] = uu - (float)x0;
    g_dy[p] = vv - (float)y0;
}

// ---------------- 2) zero padded borders (fp16, 4B stores) ----------------
__global__ void pad_kernel() {
    const int PER2 = 12352;                      // half2-pairs per plane border
    int t = blockIdx.x * 256 + threadIdx.x;
    if (t >= 2 * 8 * PER2) return;
    __half* base = (t < 8 * PER2) ? g_xm_h : g_xa_h;
    int r = t % (8 * PER2);
    int plane = r / PER2;
    int e = r % PER2;
    int y, x, ic2;
    if (e < 8256) {                              // rows 0 / 129
        y = (e < 4128) ? 0 : 129;
        int o = e % 4128; x = o >> 4; ic2 = o & 15;
    } else {                                     // cols 0 / 257
        int e2 = e - 8256;
        x = (e2 < 2048) ? 0 : 257;
        int o = e2 & 2047; y = 1 + (o >> 4); ic2 = o & 15;
    }
    *(uint32_t*)(base + ((size_t)(plane * XPH + y) * XPW + x) * 32 + ic2 * 2) = 0u;
}

// ---------------- 3) weights -> [chunk][oc][ic32] fp16 ----------------
__global__ void wtprep_kernel(const float* __restrict__ wf) {
    int idx = blockIdx.x * 256 + threadIdx.x;
    if (idx >= 18 * 2048) return;
    int ch = idx >> 11, rr = idx & 2047;
    int oc = rr >> 5, ic = rr & 31;
    int icc = ch / 9, kk = ch % 9;
    g_wt_h[idx] = __float2half(wf[(oc * 64 + icc * 32 + ic) * 9 + kk]);
}

// ---------------- 4) m: NCHW -> padded NHWC fp16 (vectorized) ----------------
__global__ __launch_bounds__(256) void nchw2xp_kernel(const float* __restrict__ m) {
    __shared__ float sm[64][33];
    int blk = blockIdx.x;                        // b*1024 + y*8 + xt
    int xt = blk & 7, y = (blk >> 3) & 127, b = blk >> 10;
    int tid = threadIdx.x;
    int c = tid & 63, pq = tid >> 6;             // 4 quarter-slots of 8 px
    const float4* src = (const float4*)(m + (((size_t)(b * 64 + c)) * 128 + y) * 256 + xt * 32);
    #pragma unroll
    for (int k = 0; k < 2; k++) {
        float4 v = src[pq * 2 + k];
        int px = (pq * 2 + k) * 4;
        sm[c][px] = v.x; sm[c][px + 1] = v.y; sm[c][px + 2] = v.z; sm[c][px + 3] = v.w;
    }
    __syncthreads();
    #pragma unroll
    for (int k = 0; k < 2; k++) {
        int j = tid + k * 256;                   // 512 uint2 writes
        int px = j >> 4, c0 = (j & 15) * 4, icc = c0 >> 5;
        uint2 pk = make_uint2(h2u(__floats2half2_rn(sm[c0][px],     sm[c0 + 1][px])),
                              h2u(__floats2half2_rn(sm[c0 + 2][px], sm[c0 + 3][px])));
        *(uint2*)(g_xm_h + (((size_t)((b * 2 + icc) * XPH) + y + 1) * XPW + xt * 32 + px + 1) * 32
                  + (c0 & 31)) = pk;
    }
}

// ---------------- 5) bilinear cube gather -> padded NHWC aux fp16 ----------------
__global__ __launch_bounds__(256) void gather_kernel(
    const float* __restrict__ fb, const float* __restrict__ fd,
    const float* __restrict__ ff, const float* __restrict__ fl,
    const float* __restrict__ fr, const float* __restrict__ fu)
{
    __shared__ float sm[64][33];
    int blk = blockIdx.x;
    int xt = blk & 7, y = (blk >> 3) & 127, b = blk >> 10;
    int tid = threadIdx.x;
    int xl = tid & 31, cw = tid >> 5;
    int p = y * 256 + xt * 32 + xl;
    int geo = g_geo[p];
    int face = geo & 7;
    int x0 = (geo >> 3) & 127, y0 = (geo >> 10) & 127;
    int x1 = (geo >> 17) & 127, y1 = (geo >> 24) & 127;
    float dx = g_dx[p], dy = g_dy[p];
    float w00 = (1.f - dx) * (1.f - dy), w01 = dx * (1.f - dy);
    float w10 = (1.f - dx) * dy,         w11 = dx * dy;
    const float* fp0;
    switch (face) {
        case 0: fp0 = fb; break; case 1: fp0 = fd; break; case 2: fp0 = ff; break;
        case 3: fp0 = fl; break; case 4: fp0 = fr; break; default: fp0 = fu; break;
    }
    #pragma unroll
    for (int k = 0; k < 8; k++) {
        int c = cw + k * 8;
        const float* fp = fp0 + ((size_t)(b * 64 + c)) * (FH * FH);
        sm[c][xl] = fp[y0 * FH + x0] * w00 + fp[y0 * FH + x1] * w01
                  + fp[y1 * FH + x0] * w10 + fp[y1 * FH + x1] * w11;
    }
    __syncthreads();
    #pragma unroll
    for (int k = 0; k < 2; k++) {
        int j = tid + k * 256;
        int px = j >> 4, c0 = (j & 15) * 4, icc = c0 >> 5;
        uint2 pk = make_uint2(h2u(__floats2half2_rn(sm[c0][px],     sm[c0 + 1][px])),
                              h2u(__floats2half2_rn(sm[c0 + 2][px], sm[c0 + 3][px])));
        *(uint2*)(g_xa_h + (((size_t)((b * 2 + icc) * XPH) + y + 1) * XPW + xt * 32 + px + 1) * 32
                  + (c0 & 31)) = pk;
    }
}

// ---------------- 6) fused: both convs (mma fp16, half-row CTA) + mask + blend ----------------
// CTA = 128 output px of one row; 256 threads, 8 warps x 16 px.
// smem bytes:
//   [0, 30720)       wt bufs: 2 stages x 3 chunks x 5120B
//   [30720, 72320)   row bufs: 2 stages x 2 slabs x 130 px x 80B (10400/slab)
//   [72320, ...)     bias 64f, wm 128f, bm 1f, maskS 128f
//   epilogue reuse: stage [128][65] f32 at 30720 (33280B)
#define SB_WT  0
#define SB_ROW 30720
#define SB_PAR 72320
#define SMEMB  73664

__global__ __launch_bounds__(256) void fused_kernel(
    const float* __restrict__ m_in, const float* __restrict__ bfu,
    const float* __restrict__ wm,   const float* __restrict__ bm,
    float* __restrict__ out)
{
    extern __shared__ char smc[];
    const uint32_t sb = smem_u32(smc);
    const int tid = threadIdx.x;
    const int wid = tid >> 5;
    const int lane = tid & 31;
    const int r4 = lane >> 2, c4 = lane & 3;
    const int half = blockIdx.x & 1;
    const int y = (blockIdx.x >> 1) & 127;
    const int b = blockIdx.x >> 8;
    const int hp = half * 128;                   // padded-col base of this half-row

    float* sbias = (float*)(smc + SB_PAR);
    float* swm   = (float*)(smc + SB_PAR + 256);
    float* sbm   = (float*)(smc + SB_PAR + 768);
    float* maskS = (float*)(smc + SB_PAR + 784);
    if (tid < 64)  sbias[tid] = bfu[tid];
    if (tid < 128) swm[tid]   = wm[tid];
    if (tid == 0)  sbm[0]     = bm[0];

    float acc[2][8][4];                          // [conv][nt][frag]
    #pragma unroll
    for (int v = 0; v < 2; v++)
        #pragma unroll
        for (int nt = 0; nt < 8; nt++)
            #pragma unroll
            for (int e = 0; e < 4; e++) acc[v][nt][e] = 0.f;

    // fill stage s: rows (2 slabs x 130 px x 4 cp16 = 1040) + weights (3 x 320 cp16)
    auto fill = [&](int s) {
        int icc = s / 3, ky = s % 3;
        size_t rowoff = ((size_t)((b * 2 + icc) * XPH + y + ky)) * XPW * 32;
        const __half* rm = g_xm_h + rowoff;
        const __half* ra = g_xa_h + rowoff;
        uint32_t rdst = sb + SB_ROW + (s & 1) * 20800;
        uint32_t wdst = sb + SB_WT + (s & 1) * 15360;
        const __half* wsrc = g_wt_h + (icc * 9 + ky * 3) * 2048;
        #pragma unroll
        for (int i = 0; i < 8; i++) {
            int j = tid + i * 256;
            if (j < 1040) {
                int slab = (j >= 520);
                int jj = j - slab * 520;
                int px = jj >> 2, q = jj & 3;
                cp16(rdst + slab * 10400 + px * 80 + q * 16,
                     (slab ? ra : rm) + (hp + px) * 32 + q * 8);
            } else if (j < 2000) {
                int jj = j - 1040;
                int ch3 = jj / 320, rr = jj % 320;
                int oc = rr / 5, q = rr % 5;
                cp16(wdst + ch3 * 5120 + oc * 80 + q * 16,
                     wsrc + ch3 * 2048 + oc * 32 + q * 8);
            }
        }
    };

    fill(0);
    asm volatile("cp.async.commit_group;" ::: "memory");

    const int mq = lane >> 3, r8 = lane & 7;     // ldmatrix lane roles
    for (int s = 0; s < 6; s++) {
        __syncthreads();                         // prior stage's smem reads done
        if (s < 5) fill(s + 1);
        asm volatile("cp.async.commit_group;" ::: "memory");
        if (s < 5) asm volatile("cp.async.wait_group 1;" ::: "memory");
        else       asm volatile("cp.async.wait_group 0;" ::: "memory");
        __syncthreads();

        const uint32_t rowb = sb + SB_ROW + (s & 1) * 20800;
        const uint32_t wtb0 = sb + SB_WT + (s & 1) * 15360;

        #pragma unroll
        for (int kx = 0; kx < 3; kx++) {
            const uint32_t wtb = wtb0 + kx * 5120;
            #pragma unroll
            for (int ks = 0; ks < 2; ks++) {
                uint32_t bw[8][2];
                #pragma unroll
                for (int p = 0; p < 4; p++) {
                    uint32_t tmp[4];
                    uint32_t addr = wtb + ((p * 2 + (mq >> 1)) * 8 + r8) * 80
                                  + (mq & 1) * 16 + ks * 32;
                    ldm4(tmp, addr);
                    bw[2 * p][0] = tmp[0]; bw[2 * p][1] = tmp[1];
                    bw[2 * p + 1][0] = tmp[2]; bw[2 * p + 1][1] = tmp[3];
                }
                uint32_t am[4], aa[4];
                uint32_t aaddr = rowb + (wid * 16 + (mq & 1) * 8 + r8 + kx) * 80
                               + (mq >> 1) * 16 + ks * 32;
                ldm4(am, aaddr);
                ldm4(aa, aaddr + 10400);
                #pragma unroll
                for (int nt = 0; nt < 8; nt++) {
                    mma16(acc[0][nt], am, bw[nt]);
                    mma16(acc[1][nt], aa, bw[nt]);
                }
            }
        }
    }

    __syncthreads();                             // all MMA smem reads done before stage reuse

    // ---------------- epilogue ----------------
    float* stage = (float*)(smc + SB_ROW);       // [128][65] relu(aux), local px
    const float bmv = sbm[0];
    const int px0 = wid * 16 + r4;               // local px

    float tot[2];
    #pragma unroll
    for (int h = 0; h < 2; h++) {
        float s = 0.f;
        int px = px0 + 8 * h;
        #pragma unroll
        for (int nt = 0; nt < 8; nt++)
            #pragma unroll
            for (int j = 0; j < 2; j++) {
                int oc = nt * 8 + 2 * c4 + j;
                float bv = sbias[oc];
                float vm = fmaxf(acc[0][nt][2 * h + j] + bv, 0.f);
                float va = fmaxf(acc[1][nt][2 * h + j] + bv, 0.f);
                s += swm[oc] * vm + swm[64 + oc] * va;
                stage[px * 65 + oc] = va;
            }
        tot[h] = s;
    }
    #pragma unroll
    for (int h = 0; h < 2; h++) {
        float s = tot[h];
        s += __shfl_xor_sync(0xffffffffu, s, 1);
        s += __shfl_xor_sync(0xffffffffu, s, 2);
        if (c4 == 0)
            maskS[px0 + 8 * h] = 1.f / (1.f + expf(-(s + bmv)));
    }
    __syncthreads();

    {
        int pxl = tid & 127;
        int ocg = tid >> 7;                      // 0/1 -> oc 0..31 / 32..63
        float mk = maskS[pxl];
        int px = hp + pxl;
        #pragma unroll 8
        for (int k = 0; k < 32; k++) {
            int oc = ocg * 32 + k;
            size_t idx = (((size_t)(b * 64 + oc)) * 128 + y) * 256 + px;
            out[idx] = m_in[idx] + mk * stage[pxl * 65 + oc];
        }
    }
}

// ---------------- launch ----------------
extern "C" void kernel_launch(void* const* d_in, const int* in_sizes, int n_in,
                              void* d_out, int out_size)
{
    const float* m  = (const float*)d_in[0];
    const float* f  = (const float*)d_in[1];
    const float* r  = (const float*)d_in[2];
    const float* bb = (const float*)d_in[3];
    const float* l  = (const float*)d_in[4];
    const float* u  = (const float*)d_in[5];
    const float* d  = (const float*)d_in[6];
    const float* wf = (const float*)d_in[7];
    const float* bf = (const float*)d_in[8];
    const float* wm = (const float*)d_in[9];
    const float* bm = (const float*)d_in[10];
    float* out = (float*)d_out;

    cudaFuncSetAttribute(fused_kernel,
                         cudaFuncAttributeMaxDynamicSharedMemorySize, SMEMB);

    geom_kernel<<<128, 256>>>();
    pad_kernel<<<772, 256>>>();
    wtprep_kernel<<<144, 256>>>(wf);
    nchw2xp_kernel<<<4096, 256>>>(m);
    gather_kernel<<<4096, 256>>>(bb, d, f, l, r, u);
    fused_kernel<<<1024, 256, SMEMB>>>(m, bf, wm, bm, out);
}